// round 12
// baseline (speedup 1.0000x reference)
#include <cuda_runtime.h>

#define NQ 4
#define NL 3

// ---------- complex helpers (float2 = re, im) ----------
__device__ __forceinline__ float2 cmul(float2 a, float2 b) {
    return make_float2(fmaf(a.x, b.x, -a.y * b.y),
                       fmaf(a.x, b.y,  a.y * b.x));
}

// Apply SU(2) gate [[a, b], [-conj(b), conj(a)]] on pairs split by mask M.
// All conjugations/negations fold into FFMA source sign modifiers (free).
template<int M>
__device__ __forceinline__ void apply_su2(float2* s, float2 a, float2 b) {
#pragma unroll
    for (int i = 0; i < 16; i++) {
        if (!(i & M)) {
            const float2 x0 = s[i], x1 = s[i | M];
            s[i].x     = fmaf(a.x, x0.x, fmaf(-a.y, x0.y, fmaf(b.x, x1.x, -b.y * x1.y)));
            s[i].y     = fmaf(a.x, x0.y, fmaf( a.y, x0.x, fmaf(b.x, x1.y,  b.y * x1.x)));
            s[i | M].x = fmaf(-b.x, x0.x, fmaf(-b.y, x0.y, fmaf(a.x, x1.x,  a.y * x1.y)));
            s[i | M].y = fmaf(-b.x, x0.y, fmaf( b.y, x0.x, fmaf(a.x, x1.y, -a.y * x1.x)));
        }
    }
}

// CNOT = compile-time permutation (free register renames after unroll)
template<int CM, int TM>
__device__ __forceinline__ void apply_cnot(float2* s) {
#pragma unroll
    for (int i = 0; i < 16; i++) {
        if ((i & CM) && !(i & TM)) { float2 t = s[i]; s[i] = s[i | TM]; s[i | TM] = t; }
    }
}

// Merged gate M = Rot * RX(x) is SU(2): top row (a,b) from batch-shared Rot
// top row (R0,R1) and per-thread c = cos(x/2), s = sin(x/2).
__device__ __forceinline__ void make_su2(float c, float s, float2 R0, float2 R1,
                                         float2& a, float2& b) {
    a.x = fmaf(s,  R1.y, c * R0.x);
    a.y = fmaf(-s, R1.x, c * R0.y);
    b.x = fmaf(s,  R0.y, c * R1.x);
    b.y = fmaf(-s, R0.x, c * R1.y);
}

__global__ void __launch_bounds__(192, 7)   // cap 48 regs (same as R8) but 42 resident warps
qfe_kernel(const float* __restrict__ x, const float* __restrict__ w,
           float* __restrict__ out, int B)
{
    // Batch-shared Rot top row per (layer, qubit): [0]=u00, [1]=u01.
    // (Rot is SU(2): u10 = -conj(u01), u11 = conj(u00).)
    __shared__ float2 gr[NL][NQ][2];
    const int tid = threadIdx.x;
    if (tid < NL * NQ) {
        const int layer = tid / NQ, q = tid % NQ;
        const float phi = w[(layer * NQ + q) * 3 + 0];
        const float th  = w[(layer * NQ + q) * 3 + 1];
        const float om  = w[(layer * NQ + q) * 3 + 2];
        float ct, st, sp, cp, sm, cm;
        sincosf(0.5f * th, &st, &ct);
        sincosf(0.5f * (phi + om), &sp, &cp);
        sincosf(0.5f * (phi - om), &sm, &cm);
        gr[layer][q][0] = make_float2( cp * ct, -sp * ct);   // u00
        gr[layer][q][1] = make_float2(-cm * st, -sm * st);   // u01
    }
    __syncthreads();

    const int b = blockIdx.x * blockDim.x + tid;
    if (b >= B) return;

    const float4 xv = reinterpret_cast<const float4*>(x)[b];
    float c_[4], s_[4];
    __sincosf(0.5f * xv.x, &s_[0], &c_[0]);
    __sincosf(0.5f * xv.y, &s_[1], &c_[1]);
    __sincosf(0.5f * xv.z, &s_[2], &c_[2]);
    __sincosf(0.5f * xv.w, &s_[3], &c_[3]);

    // ---- Layer 0: product state. M_q|0> = column 0 = (a, -conj(b)) ----
    float2 wv[4][2];
#pragma unroll
    for (int q = 0; q < 4; q++) {
        float2 a, bb;
        make_su2(c_[q], s_[q], gr[0][q][0], gr[0][q][1], a, bb);
        wv[q][0] = a;
        wv[q][1] = make_float2(-bb.x, bb.y);   // -conj(b); negs fold into cmul FMAs
    }
    float2 s[16];
    {   // balanced tensor product: (q0 (x) q1) (x) (q2 (x) q3)
        float2 t01[4], t23[4];
#pragma unroll
        for (int i = 0; i < 4; i++) {
            t01[i] = cmul(wv[0][i >> 1], wv[1][i & 1]);
            t23[i] = cmul(wv[2][i >> 1], wv[3][i & 1]);
        }
#pragma unroll
        for (int i = 0; i < 16; i++)
            s[i] = cmul(t01[i >> 2], t23[i & 3]);
    }
    apply_cnot<8, 4>(s);
    apply_cnot<4, 2>(s);
    apply_cnot<2, 1>(s);

    // ---- Layer 1: full 4-qubit sweep ----
    {
        float2 a, bb;
        make_su2(c_[0], s_[0], gr[1][0][0], gr[1][0][1], a, bb); apply_su2<8>(s, a, bb);
        make_su2(c_[1], s_[1], gr[1][1][0], gr[1][1][1], a, bb); apply_su2<4>(s, a, bb);
        make_su2(c_[2], s_[2], gr[1][2][0], gr[1][2][1], a, bb); apply_su2<2>(s, a, bb);
        make_su2(c_[3], s_[3], gr[1][3][0], gr[1][3][1], a, bb); apply_su2<1>(s, a, bb);
    }
    apply_cnot<8, 4>(s);
    apply_cnot<4, 2>(s);
    apply_cnot<2, 1>(s);

    // ---- Layer 2: q0..q2 normally ----
    {
        float2 a, bb;
        make_su2(c_[0], s_[0], gr[2][0][0], gr[2][0][1], a, bb); apply_su2<8>(s, a, bb);
        make_su2(c_[1], s_[1], gr[2][1][0], gr[2][1][1], a, bb); apply_su2<4>(s, a, bb);
        make_su2(c_[2], s_[2], gr[2][2][0], gr[2][2][1], a, bb); apply_su2<2>(s, a, bb);
    }

    // ---- q3 gate fused with probabilities + sign-transformed Walsh ----
    // Final CNOT chain only permutes indices; folded into the Z signs:
    //   z0: (-1)^{b0}, z1: (-1)^{b0^b1}, z2: (-1)^{b0^b1^b2},
    //   z3: (-1)^{b0^b1^b2^b3}   (b0 = bit8 ... b3 = bit1 of pre-CNOT index)
    // Pair over b3: n = |x0|^2+|x1|^2 (gate-invariant), plo = |y0|^2,
    // d = plo - phi = 2*plo - n.  z0..z2 need only n; z3 needs d.
    float n[8], d[8];
    {
        float2 a, bb;
        make_su2(c_[3], s_[3], gr[2][3][0], gr[2][3][1], a, bb);
#pragma unroll
        for (int j = 0; j < 8; j++) {
            const float2 x0 = s[2*j], x1 = s[2*j + 1];
            const float y0x = fmaf(a.x, x0.x, fmaf(-a.y, x0.y, fmaf(bb.x, x1.x, -bb.y * x1.y)));
            const float y0y = fmaf(a.x, x0.y, fmaf( a.y, x0.x, fmaf(bb.x, x1.y,  bb.y * x1.x)));
            n[j] = fmaf(x0.x, x0.x, fmaf(x0.y, x0.y, fmaf(x1.x, x1.x, x1.y * x1.y)));
            const float plo = fmaf(y0x, y0x, y0y * y0y);
            d[j] = fmaf(2.0f, plo, -n[j]);
        }
    }
    // pair index j bits: (b0,b1,b2) = (j&4, j&2, j&1)
    float s1[4], t1[4];
#pragma unroll
    for (int i = 0; i < 4; i++) { s1[i] = n[2*i] + n[2*i+1]; t1[i] = n[2*i] - n[2*i+1]; }
    const float z2 = (t1[0] - t1[1]) - (t1[2] - t1[3]);
    const float z1 = (s1[0] - s1[1]) - (s1[2] - s1[3]);
    const float z0 = (s1[0] + s1[1]) - (s1[2] + s1[3]);
    const float z3 = ((d[0] - d[1]) - (d[2] - d[3])) - ((d[4] - d[5]) - (d[6] - d[7]));

    reinterpret_cast<float4*>(out)[b] = make_float4(z0, z1, z2, z3);
}

extern "C" void kernel_launch(void* const* d_in, const int* in_sizes, int n_in,
                              void* d_out, int out_size) {
    const float* x = nullptr;
    const float* w = nullptr;
    int B = 0;
    for (int i = 0; i < n_in; i++) {
        if (in_sizes[i] == NL * NQ * 3) {
            w = (const float*)d_in[i];
        } else {
            x = (const float*)d_in[i];
            B = in_sizes[i] / NQ;
        }
    }
    float* out = (float*)d_out;
    const int threads = 192;
    const int blocks = (B + threads - 1) / threads;
    qfe_kernel<<<blocks, threads>>>(x, w, out, B);
}

// round 15
// speedup vs baseline: 1.1366x; 1.1366x over previous
#include <cuda_runtime.h>

#define NQ 4
#define NL 3

// ---------- complex helpers (float2 = re, im) ----------
__device__ __forceinline__ float2 cmul(float2 a, float2 b) {
    return make_float2(fmaf(a.x, b.x, -a.y * b.y),
                       fmaf(a.x, b.y,  a.y * b.x));
}

// Apply SU(2) gate [[a, b], [-conj(b), conj(a)]] on pairs split by mask M.
// All conjugations/negations fold into FFMA source sign modifiers (free).
template<int M>
__device__ __forceinline__ void apply_su2(float2* s, float2 a, float2 b) {
#pragma unroll
    for (int i = 0; i < 16; i++) {
        if (!(i & M)) {
            const float2 x0 = s[i], x1 = s[i | M];
            s[i].x     = fmaf(a.x, x0.x, fmaf(-a.y, x0.y, fmaf(b.x, x1.x, -b.y * x1.y)));
            s[i].y     = fmaf(a.x, x0.y, fmaf( a.y, x0.x, fmaf(b.x, x1.y,  b.y * x1.x)));
            s[i | M].x = fmaf(-b.x, x0.x, fmaf(-b.y, x0.y, fmaf(a.x, x1.x,  a.y * x1.y)));
            s[i | M].y = fmaf(-b.x, x0.y, fmaf( b.y, x0.x, fmaf(a.x, x1.y, -a.y * x1.x)));
        }
    }
}

// CNOT = compile-time permutation (free register renames after unroll)
template<int CM, int TM>
__device__ __forceinline__ void apply_cnot(float2* s) {
#pragma unroll
    for (int i = 0; i < 16; i++) {
        if ((i & CM) && !(i & TM)) { float2 t = s[i]; s[i] = s[i | TM]; s[i | TM] = t; }
    }
}

// Merged gate M = Rot * RX(x) is SU(2): top row (a,b) from batch-shared Rot
// top row (R0,R1) and per-thread c = cos(x/2), s = sin(x/2).
__device__ __forceinline__ void make_su2(float c, float s, float2 R0, float2 R1,
                                         float2& a, float2& b) {
    a.x = fmaf(s,  R1.y, c * R0.x);
    a.y = fmaf(-s, R1.x, c * R0.y);
    b.x = fmaf(s,  R0.y, c * R1.x);
    b.y = fmaf(-s, R0.x, c * R1.y);
}

// 48 regs is the proven spill-free floor (R8). __maxnreg__ pins it exactly.
// Launched with 192-thread blocks: 7 blocks x 6 warps = 42 resident warps/SM.
__global__ void __maxnreg__(48)
qfe_kernel(const float* __restrict__ x, const float* __restrict__ w,
           float* __restrict__ out, int B)
{
    // Batch-shared Rot top row per (layer, qubit): [0]=u00, [1]=u01.
    // (Rot is SU(2): u10 = -conj(u01), u11 = conj(u00).)
    __shared__ float2 gr[NL][NQ][2];
    const int tid = threadIdx.x;
    if (tid < NL * NQ) {
        const int layer = tid / NQ, q = tid % NQ;
        const float phi = w[(layer * NQ + q) * 3 + 0];
        const float th  = w[(layer * NQ + q) * 3 + 1];
        const float om  = w[(layer * NQ + q) * 3 + 2];
        float ct, st, sp, cp, sm, cm;
        sincosf(0.5f * th, &st, &ct);
        sincosf(0.5f * (phi + om), &sp, &cp);
        sincosf(0.5f * (phi - om), &sm, &cm);
        gr[layer][q][0] = make_float2( cp * ct, -sp * ct);   // u00
        gr[layer][q][1] = make_float2(-cm * st, -sm * st);   // u01
    }
    __syncthreads();

    const int b = blockIdx.x * blockDim.x + tid;
    if (b >= B) return;

    const float4 xv = reinterpret_cast<const float4*>(x)[b];
    float c_[4], s_[4];
    __sincosf(0.5f * xv.x, &s_[0], &c_[0]);
    __sincosf(0.5f * xv.y, &s_[1], &c_[1]);
    __sincosf(0.5f * xv.z, &s_[2], &c_[2]);
    __sincosf(0.5f * xv.w, &s_[3], &c_[3]);

    // ---- Layer 0: product state. M_q|0> = column 0 = (a, -conj(b)) ----
    float2 wv[4][2];
#pragma unroll
    for (int q = 0; q < 4; q++) {
        float2 a, bb;
        make_su2(c_[q], s_[q], gr[0][q][0], gr[0][q][1], a, bb);
        wv[q][0] = a;
        wv[q][1] = make_float2(-bb.x, bb.y);   // -conj(b); negs fold into cmul FMAs
    }
    float2 s[16];
    {   // balanced tensor product: (q0 (x) q1) (x) (q2 (x) q3)
        float2 t01[4], t23[4];
#pragma unroll
        for (int i = 0; i < 4; i++) {
            t01[i] = cmul(wv[0][i >> 1], wv[1][i & 1]);
            t23[i] = cmul(wv[2][i >> 1], wv[3][i & 1]);
        }
#pragma unroll
        for (int i = 0; i < 16; i++)
            s[i] = cmul(t01[i >> 2], t23[i & 3]);
    }
    apply_cnot<8, 4>(s);
    apply_cnot<4, 2>(s);
    apply_cnot<2, 1>(s);

    // ---- Layer 1: full 4-qubit sweep ----
    {
        float2 a, bb;
        make_su2(c_[0], s_[0], gr[1][0][0], gr[1][0][1], a, bb); apply_su2<8>(s, a, bb);
        make_su2(c_[1], s_[1], gr[1][1][0], gr[1][1][1], a, bb); apply_su2<4>(s, a, bb);
        make_su2(c_[2], s_[2], gr[1][2][0], gr[1][2][1], a, bb); apply_su2<2>(s, a, bb);
        make_su2(c_[3], s_[3], gr[1][3][0], gr[1][3][1], a, bb); apply_su2<1>(s, a, bb);
    }
    apply_cnot<8, 4>(s);
    apply_cnot<4, 2>(s);
    apply_cnot<2, 1>(s);

    // ---- Layer 2: q0..q2 normally ----
    {
        float2 a, bb;
        make_su2(c_[0], s_[0], gr[2][0][0], gr[2][0][1], a, bb); apply_su2<8>(s, a, bb);
        make_su2(c_[1], s_[1], gr[2][1][0], gr[2][1][1], a, bb); apply_su2<4>(s, a, bb);
        make_su2(c_[2], s_[2], gr[2][2][0], gr[2][2][1], a, bb); apply_su2<2>(s, a, bb);
    }

    // ---- q3 gate fused with probabilities + sign-transformed Walsh ----
    // Final CNOT chain only permutes indices; folded into the Z signs:
    //   z0: (-1)^{b0}, z1: (-1)^{b0^b1}, z2: (-1)^{b0^b1^b2},
    //   z3: (-1)^{b0^b1^b2^b3}   (b0 = bit8 ... b3 = bit1 of pre-CNOT index)
    // Pair over b3: n = |x0|^2+|x1|^2 (gate-invariant), plo = |y0|^2,
    // d = plo - phi = 2*plo - n.  z0..z2 need only n; z3 needs d.
    float n[8], d[8];
    {
        float2 a, bb;
        make_su2(c_[3], s_[3], gr[2][3][0], gr[2][3][1], a, bb);
#pragma unroll
        for (int j = 0; j < 8; j++) {
            const float2 x0 = s[2*j], x1 = s[2*j + 1];
            const float y0x = fmaf(a.x, x0.x, fmaf(-a.y, x0.y, fmaf(bb.x, x1.x, -bb.y * x1.y)));
            const float y0y = fmaf(a.x, x0.y, fmaf( a.y, x0.x, fmaf(bb.x, x1.y,  bb.y * x1.x)));
            n[j] = fmaf(x0.x, x0.x, fmaf(x0.y, x0.y, fmaf(x1.x, x1.x, x1.y * x1.y)));
            const float plo = fmaf(y0x, y0x, y0y * y0y);
            d[j] = fmaf(2.0f, plo, -n[j]);
        }
    }
    // pair index j bits: (b0,b1,b2) = (j&4, j&2, j&1)
    float s1[4], t1[4];
#pragma unroll
    for (int i = 0; i < 4; i++) { s1[i] = n[2*i] + n[2*i+1]; t1[i] = n[2*i] - n[2*i+1]; }
    const float z2 = (t1[0] - t1[1]) - (t1[2] - t1[3]);
    const float z1 = (s1[0] - s1[1]) - (s1[2] - s1[3]);
    const float z0 = (s1[0] + s1[1]) - (s1[2] + s1[3]);
    const float z3 = ((d[0] - d[1]) - (d[2] - d[3])) - ((d[4] - d[5]) - (d[6] - d[7]));

    reinterpret_cast<float4*>(out)[b] = make_float4(z0, z1, z2, z3);
}

extern "C" void kernel_launch(void* const* d_in, const int* in_sizes, int n_in,
                              void* d_out, int out_size) {
    const float* x = nullptr;
    const float* w = nullptr;
    int B = 0;
    for (int i = 0; i < n_in; i++) {
        if (in_sizes[i] == NL * NQ * 3) {
            w = (const float*)d_in[i];
        } else {
            x = (const float*)d_in[i];
            B = in_sizes[i] / NQ;
        }
    }
    float* out = (float*)d_out;
    const int threads = 192;
    const int blocks = (B + threads - 1) / threads;
    qfe_kernel<<<blocks, threads>>>(x, w, out, B);
}